// round 2
// baseline (speedup 1.0000x reference)
#include <cuda_runtime.h>

#define NEG_SLOPE 0.2f

// Node-sized scratch (N = 100000, capacity 131072)
static __device__ float g_h[131072];
static __device__ float g_asrc[131072];
static __device__ float g_adst[131072];
static __device__ float g_s[131072];
static __device__ float g_eself[131072];
// Edge-sized scratch (E = 3,200,000, capacity 3,300,000)
static __device__ int g_src[3300000];
static __device__ int g_dst[3300000];
static __device__ int g_is64;

__device__ __forceinline__ float lrelu(float e) {
    return e > 0.0f ? e : NEG_SLOPE * e;
}

// K0: probe edge_index dtype. If int64 (little-endian, values < 2^31),
// every odd int32 slot in the first 2E int32 words is the zero high-half.
__global__ void k_detect(const int* __restrict__ ei32, int E) {
    if (threadIdx.x != 0 || blockIdx.x != 0) return;
    int stride = (2 * E) / 64;          // stay within first 2E int32 words (safe for both dtypes)
    int all_zero = 1;
    for (int k = 0; k < 64; k++) {
        if (ei32[1 + (size_t)k * stride] != 0) { all_zero = 0; break; }
    }
    g_is64 = all_zero;
}

// K1: one warp per node. h = dot(x_row, W); a_src/a_dst; seed s with self-loop exp.
__global__ void k_node1(const float* __restrict__ x, const float* __restrict__ W,
                        const float* __restrict__ att_src, const float* __restrict__ att_dst,
                        int N) {
    __shared__ float sW[128];
    int tid = threadIdx.x;
    if (tid < 128) sW[tid] = W[tid];
    __syncthreads();

    int warp = (blockIdx.x * blockDim.x + tid) >> 5;
    int lane = tid & 31;
    if (warp >= N) return;

    const float4* xr = reinterpret_cast<const float4*>(x + (size_t)warp * 128);
    float4 v = xr[lane];
    float4 w = reinterpret_cast<const float4*>(sW)[lane];
    float acc = v.x * w.x + v.y * w.y + v.z * w.z + v.w * w.w;
#pragma unroll
    for (int o = 16; o; o >>= 1) acc += __shfl_xor_sync(0xFFFFFFFFu, acc, o);

    if (lane == 0) {
        float h  = acc;
        float as = h * att_src[0];
        float ad = h * att_dst[0];
        float p  = expf(lrelu(as + ad));   // self-loop term (src=dst=node)
        g_h[warp]     = h;
        g_asrc[warp]  = as;
        g_adst[warp]  = ad;
        g_eself[warp] = p;
        g_s[warp]     = p;                 // init s with self-loop contribution
    }
}

// K2: read edge_index once (dtype-flexible), cache as int32, accumulate denominator.
__global__ void k_edge1(const void* __restrict__ ei, int E, int N) {
    int j = blockIdx.x * blockDim.x + threadIdx.x;
    if (j >= E) return;
    int s, d;
    if (g_is64) {
        const long long* e64 = (const long long*)ei;
        s = (int)e64[j];
        d = (int)e64[(size_t)E + j];
    } else {
        const int* e32 = (const int*)ei;
        s = e32[j];
        d = e32[(size_t)E + j];
    }
    if ((unsigned)s >= (unsigned)N) s = 0;   // safety clamp
    if ((unsigned)d >= (unsigned)N) d = 0;
    g_src[j] = s;
    g_dst[j] = d;
    float p = expf(lrelu(g_asrc[s] + g_adst[d]));
    atomicAdd(&g_s[d], p);
}

// K3: self-loop alpha + score init (bias + self message), self-loop output slots.
__global__ void k_node2(float* __restrict__ out, const float* __restrict__ bias,
                        int N, long long E, long long M, int full) {
    int i = blockIdx.x * blockDim.x + threadIdx.x;
    if (i >= N) return;
    float alpha = g_eself[i] / (g_s[i] + 1e-16f);
    out[i] = bias[0] + g_h[i] * alpha;     // plain store BEFORE edge atomics (K4)
    if (full) {
        size_t base = (size_t)N;
        out[base + E + i]           = (float)i;  // src row, self-loop slot
        out[base + M + E + i]       = (float)i;  // dst row, self-loop slot
        out[base + 2 * M + E + i]   = alpha;     // alpha, self-loop slot
    }
}

// K4: per-edge alpha + scatter message; also emit float index copies.
__global__ void k_edge2(float* __restrict__ out, int E, long long N, long long M, int full) {
    int j = blockIdx.x * blockDim.x + threadIdx.x;
    if (j >= E) return;
    int s = g_src[j];
    int d = g_dst[j];
    float p = expf(lrelu(g_asrc[s] + g_adst[d]));  // bit-identical to K2's value
    float alpha = p / (g_s[d] + 1e-16f);
    if (full) {
        size_t base = (size_t)N;
        out[base + j]         = (float)s;
        out[base + M + j]     = (float)d;
        out[base + 2 * M + j] = alpha;
    }
    atomicAdd(&out[d], g_h[s] * alpha);
}

extern "C" void kernel_launch(void* const* d_in, const int* in_sizes, int n_in,
                              void* d_out, int out_size) {
    const float* x       = (const float*)d_in[0];
    const void*  ei      = d_in[1];
    const float* W       = (const float*)d_in[2];
    const float* att_src = (const float*)d_in[3];
    const float* att_dst = (const float*)d_in[4];
    const float* bias    = (const float*)d_in[5];

    int N = in_sizes[0] / 128;
    int E = in_sizes[1] / 2;
    long long M = (long long)E + N;
    int full = ((long long)out_size >= (long long)N + 3 * M) ? 1 : 0;
    float* out = (float*)d_out;

    // K0: dtype probe (one thread)
    k_detect<<<1, 32>>>((const int*)ei, E);
    // K1: 256 threads = 8 warps/block, one warp per node
    int wpb = 256 / 32;
    k_node1<<<(N + wpb - 1) / wpb, 256>>>(x, W, att_src, att_dst, N);
    // K2: denominator accumulation
    k_edge1<<<(E + 255) / 256, 256>>>(ei, E, N);
    // K3: score init + self-loop outputs (must precede K4's atomics)
    k_node2<<<(N + 255) / 256, 256>>>(out, bias, N, (long long)E, M, full);
    // K4: edge alpha + scatter
    k_edge2<<<(E + 255) / 256, 256>>>(out, E, (long long)N, M, full);
}

// round 4
// speedup vs baseline: 1.1422x; 1.1422x over previous
#include <cuda_runtime.h>

#define NEG_SLOPE 0.2f

// Node-sized scratch (N = 100000, capacity 131072)
// spack[i] = {a_src[i], h[i]}        (indexed by src)
// dpack[i] = {a_dst[i], s_denom[i]}  (indexed by dst; .y accumulated by K2 atomics)
static __device__ float2 g_spack[131072];
static __device__ float2 g_dpack[131072];
static __device__ float  g_eself[131072];
static __device__ int    g_is64;

__device__ __forceinline__ float lrelu(float e) {
    return e > 0.0f ? e : NEG_SLOPE * e;
}

// K0: parallel dtype probe. int64 little-endian with values < 2^31 => odd int32 slots all zero.
__global__ void k_detect(const int* __restrict__ ei32, int E) {
    __shared__ int nz;
    if (threadIdx.x == 0) nz = 0;
    __syncthreads();
    int stride = (2 * E) / 64;
    int v = ei32[1 + (size_t)threadIdx.x * stride];   // 64 independent loads, fully overlapped
    if (v != 0) atomicAdd(&nz, 1);
    __syncthreads();
    if (threadIdx.x == 0) g_is64 = (nz == 0);
}

// K1: one warp per node. h = dot(x_row, W); pack attention scalars; seed denom with self-loop.
__global__ void k_node1(const float* __restrict__ x, const float* __restrict__ W,
                        const float* __restrict__ att_src, const float* __restrict__ att_dst,
                        int N) {
    __shared__ float sW[128];
    int tid = threadIdx.x;
    if (tid < 128) sW[tid] = W[tid];
    __syncthreads();

    int warp = (blockIdx.x * blockDim.x + tid) >> 5;
    int lane = tid & 31;
    if (warp >= N) return;

    const float4* xr = reinterpret_cast<const float4*>(x + (size_t)warp * 128);
    float4 v = xr[lane];
    float4 w = reinterpret_cast<const float4*>(sW)[lane];
    float acc = v.x * w.x + v.y * w.y + v.z * w.z + v.w * w.w;
#pragma unroll
    for (int o = 16; o; o >>= 1) acc += __shfl_xor_sync(0xFFFFFFFFu, acc, o);

    if (lane == 0) {
        float h  = acc;
        float as = h * att_src[0];
        float ad = h * att_dst[0];
        float p  = expf(lrelu(as + ad));           // self-loop term
        g_spack[warp] = make_float2(as, h);
        g_dpack[warp] = make_float2(ad, p);        // denom seeded with self-loop
        g_eself[warp] = p;
    }
}

// Edge-index fetch helper: 4 consecutive edges starting at base (base+4 <= E, fast path).
__device__ __forceinline__ void load_edges4(const void* __restrict__ ei, int E, int N,
                                            int base, int* s, int* d) {
    if (!g_is64) {
        const int* e32 = (const int*)ei;
        int4 sv = *reinterpret_cast<const int4*>(e32 + base);
        int4 dv = *reinterpret_cast<const int4*>(e32 + (size_t)E + base);
        s[0] = sv.x; s[1] = sv.y; s[2] = sv.z; s[3] = sv.w;
        d[0] = dv.x; d[1] = dv.y; d[2] = dv.z; d[3] = dv.w;
    } else {
        const long long* e64 = (const long long*)ei;
#pragma unroll
        for (int k = 0; k < 4; k++) {
            s[k] = (int)e64[base + k];
            d[k] = (int)e64[(size_t)E + base + k];
        }
    }
#pragma unroll
    for (int k = 0; k < 4; k++) {
        if ((unsigned)s[k] >= (unsigned)N) s[k] = 0;
        if ((unsigned)d[k] >= (unsigned)N) d[k] = 0;
    }
}

__device__ __forceinline__ void load_edge1(const void* __restrict__ ei, int E, int N,
                                           int j, int& s, int& d) {
    if (!g_is64) {
        const int* e32 = (const int*)ei;
        s = e32[j];
        d = e32[(size_t)E + j];
    } else {
        const long long* e64 = (const long long*)ei;
        s = (int)e64[j];
        d = (int)e64[(size_t)E + j];
    }
    if ((unsigned)s >= (unsigned)N) s = 0;
    if ((unsigned)d >= (unsigned)N) d = 0;
}

// K2: 4 edges/thread; accumulate softmax denominator into g_dpack[].y.
__global__ void k_edge1(const void* __restrict__ ei, int E, int N) {
    int base = (blockIdx.x * blockDim.x + threadIdx.x) * 4;
    if (base >= E) return;
    if (base + 4 <= E) {
        int s[4], d[4];
        load_edges4(ei, E, N, base, s, d);
#pragma unroll
        for (int k = 0; k < 4; k++) {
            float p = expf(lrelu(g_spack[s[k]].x + g_dpack[d[k]].x));
            atomicAdd(&g_dpack[d[k]].y, p);
        }
    } else {
        for (int j = base; j < E; j++) {
            int s, d;
            load_edge1(ei, E, N, j, s, d);
            float p = expf(lrelu(g_spack[s].x + g_dpack[d].x));
            atomicAdd(&g_dpack[d].y, p);
        }
    }
}

// K3: self-loop alpha + score init + self-loop output slots.
__global__ void k_node2(float* __restrict__ out, const float* __restrict__ bias,
                        int N, long long E, long long M, int full) {
    int i = blockIdx.x * blockDim.x + threadIdx.x;
    if (i >= N) return;
    float2 dp = g_dpack[i];
    float2 sp = g_spack[i];
    float alpha = g_eself[i] / (dp.y + 1e-16f);
    out[i] = bias[0] + sp.y * alpha;               // plain store BEFORE K4 atomics
    if (full) {
        size_t base = (size_t)N;
        float fi = (float)i;
        out[base + E + i]         = fi;            // src, self-loop slot
        out[base + M + E + i]     = fi;            // dst, self-loop slot
        out[base + 2 * M + E + i] = alpha;         // alpha, self-loop slot
    }
}

// K4: 4 edges/thread; reread ei (L2-resident), write streams as float4 (__stcs), scatter scores.
__global__ void k_edge2(const void* __restrict__ ei, float* __restrict__ out,
                        int E, int N, long long M, int full) {
    int base = (blockIdx.x * blockDim.x + threadIdx.x) * 4;
    if (base >= E) return;
    if (base + 4 <= E) {
        int s[4], d[4];
        load_edges4(ei, E, N, base, s, d);
        float alpha[4], msg[4];
#pragma unroll
        for (int k = 0; k < 4; k++) {
            float2 sp = g_spack[s[k]];
            float2 dp = g_dpack[d[k]];
            float p = expf(lrelu(sp.x + dp.x));    // bit-identical to K2's value
            alpha[k] = p / (dp.y + 1e-16f);
            msg[k]   = sp.y * alpha[k];
        }
        if (full) {
            size_t b = (size_t)N + base;
            float4 fs = make_float4((float)s[0], (float)s[1], (float)s[2], (float)s[3]);
            float4 fd = make_float4((float)d[0], (float)d[1], (float)d[2], (float)d[3]);
            float4 fa = make_float4(alpha[0], alpha[1], alpha[2], alpha[3]);
            __stcs(reinterpret_cast<float4*>(out + b), fs);
            __stcs(reinterpret_cast<float4*>(out + b + M), fd);
            __stcs(reinterpret_cast<float4*>(out + b + 2 * M), fa);
        }
#pragma unroll
        for (int k = 0; k < 4; k++)
            atomicAdd(&out[d[k]], msg[k]);
    } else {
        for (int j = base; j < E; j++) {
            int s, d;
            load_edge1(ei, E, N, j, s, d);
            float2 sp = g_spack[s];
            float2 dp = g_dpack[d];
            float p = expf(lrelu(sp.x + dp.x));
            float alpha = p / (dp.y + 1e-16f);
            if (full) {
                size_t b = (size_t)N + j;
                out[b]         = (float)s;
                out[b + M]     = (float)d;
                out[b + 2 * M] = alpha;
            }
            atomicAdd(&out[d], sp.y * alpha);
        }
    }
}

extern "C" void kernel_launch(void* const* d_in, const int* in_sizes, int n_in,
                              void* d_out, int out_size) {
    const float* x       = (const float*)d_in[0];
    const void*  ei      = d_in[1];
    const float* W       = (const float*)d_in[2];
    const float* att_src = (const float*)d_in[3];
    const float* att_dst = (const float*)d_in[4];
    const float* bias    = (const float*)d_in[5];

    int N = in_sizes[0] / 128;
    int E = in_sizes[1] / 2;
    long long M = (long long)E + N;
    int full = ((long long)out_size >= (long long)N + 3 * M) ? 1 : 0;
    float* out = (float*)d_out;

    k_detect<<<1, 64>>>((const int*)ei, E);
    int wpb = 256 / 32;
    k_node1<<<(N + wpb - 1) / wpb, 256>>>(x, W, att_src, att_dst, N);
    int eth = (E + 3) / 4;                          // threads for 4-edges/thread kernels
    k_edge1<<<(eth + 255) / 256, 256>>>(ei, E, N);
    k_node2<<<(N + 255) / 256, 256>>>(out, bias, N, (long long)E, M, full);
    k_edge2<<<(eth + 255) / 256, 256>>>(ei, out, E, N, M, full);
}

// round 5
// speedup vs baseline: 1.5610x; 1.3666x over previous
#include <cuda_runtime.h>

#define NEG_SLOPE 0.2f

// Node-sized scratch (N = 100000, capacity 131072)
static __device__ float2 g_spack[131072];   // {a_src, h}  indexed by src
static __device__ float  g_ad[131072];      // a_dst       indexed by dst
static __device__ float2 g_acc[131072];     // {numer, denom} accumulated by K2 (vec atomic)
static __device__ float  g_eself[131072];   // self-loop exp term
// Edge-sized scratch: per-edge exp value p[j]
static __device__ float  g_p[3300000];
static __device__ int    g_is64;

__device__ __forceinline__ float lrelu(float e) {
    return e > 0.0f ? e : NEG_SLOPE * e;
}

__device__ __forceinline__ void red_add_v2(float2* addr, float x, float y) {
    asm volatile("red.global.add.v2.f32 [%0], {%1, %2};"
                 :: "l"(addr), "f"(x), "f"(y) : "memory");
}

// K0: parallel dtype probe. int64 little-endian with values < 2^31 => odd int32 slots all zero.
__global__ void k_detect(const int* __restrict__ ei32, int E) {
    __shared__ int nz;
    if (threadIdx.x == 0) nz = 0;
    __syncthreads();
    int stride = (2 * E) / 64;
    int v = ei32[1 + (size_t)threadIdx.x * stride];
    if (v != 0) atomicAdd(&nz, 1);
    __syncthreads();
    if (threadIdx.x == 0) g_is64 = (nz == 0);
}

// K1: one warp per node. h = dot(x_row, W); pack scalars; seed acc with self-loop terms.
__global__ void k_node1(const float* __restrict__ x, const float* __restrict__ W,
                        const float* __restrict__ att_src, const float* __restrict__ att_dst,
                        int N) {
    __shared__ float sW[128];
    int tid = threadIdx.x;
    if (tid < 128) sW[tid] = W[tid];
    __syncthreads();

    int warp = (blockIdx.x * blockDim.x + tid) >> 5;
    int lane = tid & 31;
    if (warp >= N) return;

    const float4* xr = reinterpret_cast<const float4*>(x + (size_t)warp * 128);
    float4 v = xr[lane];
    float4 w = reinterpret_cast<const float4*>(sW)[lane];
    float acc = v.x * w.x + v.y * w.y + v.z * w.z + v.w * w.w;
#pragma unroll
    for (int o = 16; o; o >>= 1) acc += __shfl_xor_sync(0xFFFFFFFFu, acc, o);

    if (lane == 0) {
        float h  = acc;
        float as = h * att_src[0];
        float ad = h * att_dst[0];
        float p  = expf(lrelu(as + ad));            // self-loop term
        g_spack[warp] = make_float2(as, h);
        g_ad[warp]    = ad;
        g_acc[warp]   = make_float2(h * p, p);      // seed {numer, denom} with self-loop
        g_eself[warp] = p;
    }
}

__device__ __forceinline__ void load_edges4(const void* __restrict__ ei, int E, int N,
                                            int base, int* s, int* d) {
    if (!g_is64) {
        const int* e32 = (const int*)ei;
        int4 sv = *reinterpret_cast<const int4*>(e32 + base);
        int4 dv = *reinterpret_cast<const int4*>(e32 + (size_t)E + base);
        s[0] = sv.x; s[1] = sv.y; s[2] = sv.z; s[3] = sv.w;
        d[0] = dv.x; d[1] = dv.y; d[2] = dv.z; d[3] = dv.w;
    } else {
        const long long* e64 = (const long long*)ei;
#pragma unroll
        for (int k = 0; k < 4; k++) {
            s[k] = (int)e64[base + k];
            d[k] = (int)e64[(size_t)E + base + k];
        }
    }
#pragma unroll
    for (int k = 0; k < 4; k++) {
        if ((unsigned)s[k] >= (unsigned)N) s[k] = 0;
        if ((unsigned)d[k] >= (unsigned)N) d[k] = 0;
    }
}

__device__ __forceinline__ void load_edge1(const void* __restrict__ ei, int E, int N,
                                           int j, int& s, int& d) {
    if (!g_is64) {
        const int* e32 = (const int*)ei;
        s = e32[j];
        d = e32[(size_t)E + j];
    } else {
        const long long* e64 = (const long long*)ei;
        s = (int)e64[j];
        d = (int)e64[(size_t)E + j];
    }
    if ((unsigned)s >= (unsigned)N) s = 0;
    if ((unsigned)d >= (unsigned)N) d = 0;
}

// K2: 4 edges/thread. Compute p; stream p to scratch; one vector atomic per edge
// accumulates {numer += h[s]*p, denom += p} into g_acc[d].
__global__ void k_edge1(const void* __restrict__ ei, int E, int N) {
    int base = (blockIdx.x * blockDim.x + threadIdx.x) * 4;
    if (base >= E) return;
    if (base + 4 <= E) {
        int s[4], d[4];
        load_edges4(ei, E, N, base, s, d);
        float2 sp[4];
        float  ad[4];
#pragma unroll
        for (int k = 0; k < 4; k++) { sp[k] = g_spack[s[k]]; ad[k] = g_ad[d[k]]; }
        float p[4];
#pragma unroll
        for (int k = 0; k < 4; k++) p[k] = expf(lrelu(sp[k].x + ad[k]));
        *reinterpret_cast<float4*>(g_p + base) = make_float4(p[0], p[1], p[2], p[3]);
#pragma unroll
        for (int k = 0; k < 4; k++)
            red_add_v2(&g_acc[d[k]], sp[k].y * p[k], p[k]);
    } else {
        for (int j = base; j < E; j++) {
            int s, d;
            load_edge1(ei, E, N, j, s, d);
            float2 sp = g_spack[s];
            float p = expf(lrelu(sp.x + g_ad[d]));
            g_p[j] = p;
            red_add_v2(&g_acc[d], sp.y * p, p);
        }
    }
}

// K3: final scores (no atomics needed anymore) + self-loop output slots.
__global__ void k_node2(float* __restrict__ out, const float* __restrict__ bias,
                        int N, long long E, long long M, int full) {
    int i = blockIdx.x * blockDim.x + threadIdx.x;
    if (i >= N) return;
    float2 acc = g_acc[i];
    float inv = 1.0f / (acc.y + 1e-16f);
    out[i] = bias[0] + acc.x * inv;
    if (full) {
        size_t base = (size_t)N;
        float fi = (float)i;
        out[base + E + i]         = fi;               // src, self-loop slot
        out[base + M + E + i]     = fi;               // dst, self-loop slot
        out[base + 2 * M + E + i] = g_eself[i] * inv; // alpha, self-loop slot
    }
}

// K4: 4 edges/thread. Coalesced reread of ei + p; ONE random gather (denom); stream outputs.
__global__ void k_edge2(const void* __restrict__ ei, float* __restrict__ out,
                        int E, int N, long long M, int full) {
    int base = (blockIdx.x * blockDim.x + threadIdx.x) * 4;
    if (base >= E) return;
    if (base + 4 <= E) {
        int s[4], d[4];
        load_edges4(ei, E, N, base, s, d);
        float4 pv = *reinterpret_cast<const float4*>(g_p + base);
        float p[4] = {pv.x, pv.y, pv.z, pv.w};
        float alpha[4];
#pragma unroll
        for (int k = 0; k < 4; k++)
            alpha[k] = p[k] / (g_acc[d[k]].y + 1e-16f);
        size_t b = (size_t)N + base;
        float4 fs = make_float4((float)s[0], (float)s[1], (float)s[2], (float)s[3]);
        float4 fd = make_float4((float)d[0], (float)d[1], (float)d[2], (float)d[3]);
        float4 fa = make_float4(alpha[0], alpha[1], alpha[2], alpha[3]);
        __stcs(reinterpret_cast<float4*>(out + b), fs);
        __stcs(reinterpret_cast<float4*>(out + b + M), fd);
        __stcs(reinterpret_cast<float4*>(out + b + 2 * M), fa);
    } else {
        for (int j = base; j < E; j++) {
            int s, d;
            load_edge1(ei, E, N, j, s, d);
            float alpha = g_p[j] / (g_acc[d].y + 1e-16f);
            size_t b = (size_t)N + j;
            out[b]         = (float)s;
            out[b + M]     = (float)d;
            out[b + 2 * M] = alpha;
        }
    }
}

// K4-lite for score-only output layouts (keeps 'full' semantics correct).
__global__ void k_edge2_lite(int dummy) {}

extern "C" void kernel_launch(void* const* d_in, const int* in_sizes, int n_in,
                              void* d_out, int out_size) {
    const float* x       = (const float*)d_in[0];
    const void*  ei      = d_in[1];
    const float* W       = (const float*)d_in[2];
    const float* att_src = (const float*)d_in[3];
    const float* att_dst = (const float*)d_in[4];
    const float* bias    = (const float*)d_in[5];

    int N = in_sizes[0] / 128;
    int E = in_sizes[1] / 2;
    long long M = (long long)E + N;
    int full = ((long long)out_size >= (long long)N + 3 * M) ? 1 : 0;
    float* out = (float*)d_out;

    k_detect<<<1, 64>>>((const int*)ei, E);
    int wpb = 256 / 32;
    k_node1<<<(N + wpb - 1) / wpb, 256>>>(x, W, att_src, att_dst, N);
    int eth = (E + 3) / 4;
    k_edge1<<<(eth + 255) / 256, 256>>>(ei, E, N);
    k_node2<<<(N + 255) / 256, 256>>>(out, bias, N, (long long)E, M, full);
    if (full)
        k_edge2<<<(eth + 255) / 256, 256>>>(ei, out, E, N, M, full);
}

// round 8
// speedup vs baseline: 1.6410x; 1.0513x over previous
#include <cuda_runtime.h>

#define NEG_SLOPE 0.2f

// Node-sized scratch (N = 100000, capacity 131072)
static __device__ float2 g_spack[131072];   // {a_src, h}  indexed by src
static __device__ float  g_ad[131072];      // a_dst (K1..K2) then REUSED as inv_denom (K3..K4)
static __device__ float2 g_acc[131072];     // {numer, denom} accumulated by K2 (vec atomic)
static __device__ float  g_eself[131072];   // self-loop exp term
// Edge-sized scratch: per-edge exp value p[j]
static __device__ float  g_p[3300000];
static __device__ int    g_is64;

__device__ __forceinline__ float lrelu(float e) {
    return e > 0.0f ? e : NEG_SLOPE * e;
}

__device__ __forceinline__ void red_add_v2(float2* addr, float x, float y) {
    asm volatile("red.global.add.v2.f32 [%0], {%1, %2};"
                 :: "l"(addr), "f"(x), "f"(y) : "memory");
}

// K0: parallel dtype probe. int64 little-endian with values < 2^31 => odd int32 slots all zero.
__global__ void k_detect(const int* __restrict__ ei32, int E) {
    __shared__ int nz;
    if (threadIdx.x == 0) nz = 0;
    __syncthreads();
    int stride = (2 * E) / 64;
    int v = ei32[1 + (size_t)threadIdx.x * stride];
    if (v != 0) atomicAdd(&nz, 1);
    __syncthreads();
    if (threadIdx.x == 0) g_is64 = (nz == 0);
}

__device__ __forceinline__ void load_edges4(const void* __restrict__ ei, int E, int N,
                                            int base, int* s, int* d) {
    if (!g_is64) {
        const int* e32 = (const int*)ei;
        int4 sv = *reinterpret_cast<const int4*>(e32 + base);
        int4 dv = *reinterpret_cast<const int4*>(e32 + (size_t)E + base);
        s[0] = sv.x; s[1] = sv.y; s[2] = sv.z; s[3] = sv.w;
        d[0] = dv.x; d[1] = dv.y; d[2] = dv.z; d[3] = dv.w;
    } else {
        const long long* e64 = (const long long*)ei;
#pragma unroll
        for (int k = 0; k < 4; k++) {
            s[k] = (int)e64[base + k];
            d[k] = (int)e64[(size_t)E + base + k];
        }
    }
#pragma unroll
    for (int k = 0; k < 4; k++) {
        if ((unsigned)s[k] >= (unsigned)N) s[k] = 0;
        if ((unsigned)d[k] >= (unsigned)N) d[k] = 0;
    }
}

__device__ __forceinline__ void load_edge1(const void* __restrict__ ei, int E, int N,
                                           int j, int& s, int& d) {
    if (!g_is64) {
        const int* e32 = (const int*)ei;
        s = e32[j];
        d = e32[(size_t)E + j];
    } else {
        const long long* e64 = (const long long*)ei;
        s = (int)e64[j];
        d = (int)e64[(size_t)E + j];
    }
    if ((unsigned)s >= (unsigned)N) s = 0;
    if ((unsigned)d >= (unsigned)N) d = 0;
}

// KC: copy edge indices to float output streams (coalesced, streaming stores).
__global__ void k_copyidx(const void* __restrict__ ei, float* __restrict__ out,
                          int E, int N, long long M) {
    int base = (blockIdx.x * blockDim.x + threadIdx.x) * 4;
    if (base >= E) return;
    if (base + 4 <= E) {
        int s[4], d[4];
        load_edges4(ei, E, N, base, s, d);
        size_t b = (size_t)N + base;
        float4 fs = make_float4((float)s[0], (float)s[1], (float)s[2], (float)s[3]);
        float4 fd = make_float4((float)d[0], (float)d[1], (float)d[2], (float)d[3]);
        __stcs(reinterpret_cast<float4*>(out + b), fs);
        __stcs(reinterpret_cast<float4*>(out + b + M), fd);
    } else {
        for (int j = base; j < E; j++) {
            int s, d;
            load_edge1(ei, E, N, j, s, d);
            out[(size_t)N + j]     = (float)s;
            out[(size_t)N + M + j] = (float)d;
        }
    }
}

// K1: one warp per node. h = dot(x_row, W); pack scalars; seed acc with self-loop terms.
// x loaded with __ldcs (read-once) to avoid evicting ei / node arrays from L2.
__global__ void k_node1(const float* __restrict__ x, const float* __restrict__ W,
                        const float* __restrict__ att_src, const float* __restrict__ att_dst,
                        int N) {
    __shared__ float sW[128];
    int tid = threadIdx.x;
    if (tid < 128) sW[tid] = W[tid];
    __syncthreads();

    int warp = (blockIdx.x * blockDim.x + tid) >> 5;
    int lane = tid & 31;
    if (warp >= N) return;

    const float4* xr = reinterpret_cast<const float4*>(x + (size_t)warp * 128);
    float4 v = __ldcs(&xr[lane]);
    float4 w = reinterpret_cast<const float4*>(sW)[lane];
    float acc = v.x * w.x + v.y * w.y + v.z * w.z + v.w * w.w;
#pragma unroll
    for (int o = 16; o; o >>= 1) acc += __shfl_xor_sync(0xFFFFFFFFu, acc, o);

    if (lane == 0) {
        float h  = acc;
        float as = h * att_src[0];
        float ad = h * att_dst[0];
        float p  = expf(lrelu(as + ad));            // self-loop term
        g_spack[warp] = make_float2(as, h);
        g_ad[warp]    = ad;
        g_acc[warp]   = make_float2(h * p, p);      // seed {numer, denom} with self-loop
        g_eself[warp] = p;
    }
}

// K2: 4 edges/thread. Compute p; stream p to scratch; one vector atomic per edge
// accumulates {numer += h[s]*p, denom += p} into g_acc[d].
__global__ void k_edge1(const void* __restrict__ ei, int E, int N) {
    int base = (blockIdx.x * blockDim.x + threadIdx.x) * 4;
    if (base >= E) return;
    if (base + 4 <= E) {
        int s[4], d[4];
        load_edges4(ei, E, N, base, s, d);
        float2 sp[4];
        float  ad[4];
#pragma unroll
        for (int k = 0; k < 4; k++) { sp[k] = g_spack[s[k]]; ad[k] = g_ad[d[k]]; }
        float p[4];
#pragma unroll
        for (int k = 0; k < 4; k++) p[k] = expf(lrelu(sp[k].x + ad[k]));
        *reinterpret_cast<float4*>(g_p + base) = make_float4(p[0], p[1], p[2], p[3]);
#pragma unroll
        for (int k = 0; k < 4; k++)
            red_add_v2(&g_acc[d[k]], sp[k].y * p[k], p[k]);
    } else {
        for (int j = base; j < E; j++) {
            int s, d;
            load_edge1(ei, E, N, j, s, d);
            float2 sp = g_spack[s];
            float p = expf(lrelu(sp.x + g_ad[d]));
            g_p[j] = p;
            red_add_v2(&g_acc[d], sp.y * p, p);
        }
    }
}

// K3: final scores + inv_denom (reusing g_ad) + self-loop output slots.
__global__ void k_node2(float* __restrict__ out, const float* __restrict__ bias,
                        int N, long long E, long long M, int full) {
    int i = blockIdx.x * blockDim.x + threadIdx.x;
    if (i >= N) return;
    float2 acc = g_acc[i];
    float inv = 1.0f / (acc.y + 1e-16f);
    g_ad[i] = inv;                                  // a_dst dead after K2; reuse as inv_denom
    out[i] = bias[0] + acc.x * inv;
    if (full) {
        size_t base = (size_t)N;
        float fi = (float)i;
        out[base + E + i]         = fi;               // src, self-loop slot
        out[base + M + E + i]     = fi;               // dst, self-loop slot
        out[base + 2 * M + E + i] = g_eself[i] * inv; // alpha, self-loop slot
    }
}

// K4: alpha only. Reads dst back from out's float-dst stream (exact for idx < 2^24),
// one random gather (inv[d]) per edge, streams alpha out.
__global__ void k_edge2(float* __restrict__ out, int E, int N, long long M) {
    int base = (blockIdx.x * blockDim.x + threadIdx.x) * 4;
    if (base >= E) return;
    size_t b = (size_t)N + base;
    if (base + 4 <= E) {
        float4 fd = *reinterpret_cast<const float4*>(out + b + M);
        float4 pv = *reinterpret_cast<const float4*>(g_p + base);
        int d0 = __float2int_rz(fd.x), d1 = __float2int_rz(fd.y);
        int d2 = __float2int_rz(fd.z), d3 = __float2int_rz(fd.w);
        float4 fa = make_float4(pv.x * g_ad[d0], pv.y * g_ad[d1],
                                pv.z * g_ad[d2], pv.w * g_ad[d3]);
        __stcs(reinterpret_cast<float4*>(out + b + 2 * M), fa);
    } else {
        for (int j = base; j < E; j++) {
            int d = __float2int_rz(out[(size_t)N + M + j]);
            out[(size_t)N + 2 * M + j] = g_p[j] * g_ad[d];
        }
    }
}

extern "C" void kernel_launch(void* const* d_in, const int* in_sizes, int n_in,
                              void* d_out, int out_size) {
    const float* x       = (const float*)d_in[0];
    const void*  ei      = d_in[1];
    const float* W       = (const float*)d_in[2];
    const float* att_src = (const float*)d_in[3];
    const float* att_dst = (const float*)d_in[4];
    const float* bias    = (const float*)d_in[5];

    int N = in_sizes[0] / 128;
    int E = in_sizes[1] / 2;
    long long M = (long long)E + N;
    int full = ((long long)out_size >= (long long)N + 3 * M) ? 1 : 0;
    float* out = (float*)d_out;

    int wpb = 256 / 32;
    int eth = (E + 3) / 4;
    int eblocks = (eth + 255) / 256;

    k_detect<<<1, 64>>>((const int*)ei, E);
    if (full)
        k_copyidx<<<eblocks, 256>>>(ei, out, E, N, M);
    k_node1<<<(N + wpb - 1) / wpb, 256>>>(x, W, att_src, att_dst, N);
    k_edge1<<<eblocks, 256>>>(ei, E, N);
    k_node2<<<(N + 255) / 256, 256>>>(out, bias, N, (long long)E, M, full);
    if (full)
        k_edge2<<<eblocks, 256>>>(out, E, N, M);
}

// round 9
// speedup vs baseline: 1.7283x; 1.0532x over previous
#include <cuda_runtime.h>

#define NEG_SLOPE 0.2f

// Node-sized scratch (N = 100000, capacity 131072)
static __device__ float2 g_spack[131072];   // {a_src, h}  indexed by src
static __device__ float  g_ad[131072];      // a_dst
static __device__ float2 g_acc[131072];     // {numer, denom} accumulated by K2 (vec atomic)
static __device__ float  g_eself[131072];   // self-loop exp term
// Edge-sized scratch: per-edge exp value p[j]
static __device__ float  g_p[3300000];

__device__ __forceinline__ float lrelu(float e) {
    return e > 0.0f ? e : NEG_SLOPE * e;
}

__device__ __forceinline__ void red_add_v2(float2* addr, float x, float y) {
    asm volatile("red.global.add.v2.f32 [%0], {%1, %2};"
                 :: "l"(addr), "f"(x), "f"(y) : "memory");
}

// Per-block dtype probe: int64 little-endian with values < 2^31 => sampled odd
// int32 slots are all zero. 64 L2-hit loads per block; no separate kernel.
__device__ __forceinline__ int probe_is64(const int* __restrict__ ei32, int E) {
    __shared__ int s_nz;
    if (threadIdx.x == 0) s_nz = 0;
    __syncthreads();
    if (threadIdx.x < 64) {
        int stride = (2 * E) / 64;
        if (ei32[1 + (size_t)threadIdx.x * stride] != 0) atomicAdd(&s_nz, 1);
    }
    __syncthreads();
    return s_nz == 0;
}

__device__ __forceinline__ void load_edges4(const void* __restrict__ ei, int E, int N,
                                            int base, int is64, int* s, int* d) {
    if (!is64) {
        const int* e32 = (const int*)ei;
        int4 sv = *reinterpret_cast<const int4*>(e32 + base);
        int4 dv = *reinterpret_cast<const int4*>(e32 + (size_t)E + base);
        s[0] = sv.x; s[1] = sv.y; s[2] = sv.z; s[3] = sv.w;
        d[0] = dv.x; d[1] = dv.y; d[2] = dv.z; d[3] = dv.w;
    } else {
        const long long* e64 = (const long long*)ei;
#pragma unroll
        for (int k = 0; k < 4; k++) {
            s[k] = (int)e64[base + k];
            d[k] = (int)e64[(size_t)E + base + k];
        }
    }
#pragma unroll
    for (int k = 0; k < 4; k++) {
        if ((unsigned)s[k] >= (unsigned)N) s[k] = 0;
        if ((unsigned)d[k] >= (unsigned)N) d[k] = 0;
    }
}

__device__ __forceinline__ void load_edge1(const void* __restrict__ ei, int E, int N,
                                           int j, int is64, int& s, int& d) {
    if (!is64) {
        const int* e32 = (const int*)ei;
        s = e32[j];
        d = e32[(size_t)E + j];
    } else {
        const long long* e64 = (const long long*)ei;
        s = (int)e64[j];
        d = (int)e64[(size_t)E + j];
    }
    if ((unsigned)s >= (unsigned)N) s = 0;
    if ((unsigned)d >= (unsigned)N) d = 0;
}

// KA (fused): blocks [0, ebA) copy edge indices to float output streams;
// blocks [ebA, ebA+nodeblocks) do the x·W node pass. Independent memory
// streams overlap inside one launch.
__global__ void k_fuseA(const void* __restrict__ ei, const float* __restrict__ x,
                        const float* __restrict__ W,
                        const float* __restrict__ att_src, const float* __restrict__ att_dst,
                        float* __restrict__ out, int E, int N, long long M, int ebA) {
    int tid = threadIdx.x;
    if ((int)blockIdx.x < ebA) {
        // ---- index-copy role ----
        int is64 = probe_is64((const int*)ei, E);
        int base = (blockIdx.x * blockDim.x + tid) * 4;
        if (base >= E) return;
        if (base + 4 <= E) {
            int s[4], d[4];
            load_edges4(ei, E, N, base, is64, s, d);
            size_t b = (size_t)N + base;
            float4 fs = make_float4((float)s[0], (float)s[1], (float)s[2], (float)s[3]);
            float4 fd = make_float4((float)d[0], (float)d[1], (float)d[2], (float)d[3]);
            __stcs(reinterpret_cast<float4*>(out + b), fs);
            __stcs(reinterpret_cast<float4*>(out + b + M), fd);
        } else {
            for (int j = base; j < E; j++) {
                int s, d;
                load_edge1(ei, E, N, j, is64, s, d);
                out[(size_t)N + j]     = (float)s;
                out[(size_t)N + M + j] = (float)d;
            }
        }
    } else {
        // ---- node pass role: one warp per node ----
        __shared__ float sW[128];
        if (tid < 128) sW[tid] = W[tid];
        __syncthreads();

        int warp = (((int)blockIdx.x - ebA) * blockDim.x + tid) >> 5;
        int lane = tid & 31;
        if (warp >= N) return;

        const float4* xr = reinterpret_cast<const float4*>(x + (size_t)warp * 128);
        float4 v = __ldcs(&xr[lane]);
        float4 w = reinterpret_cast<const float4*>(sW)[lane];
        float acc = v.x * w.x + v.y * w.y + v.z * w.z + v.w * w.w;
#pragma unroll
        for (int o = 16; o; o >>= 1) acc += __shfl_xor_sync(0xFFFFFFFFu, acc, o);

        if (lane == 0) {
            float h  = acc;
            float as = h * att_src[0];
            float ad = h * att_dst[0];
            float p  = expf(lrelu(as + ad));        // self-loop term
            g_spack[warp] = make_float2(as, h);
            g_ad[warp]    = ad;
            g_acc[warp]   = make_float2(h * p, p);  // seed {numer, denom} with self-loop
            g_eself[warp] = p;
        }
    }
}

// K2: 4 edges/thread. Compute p; stream p to scratch; one vector atomic per edge
// accumulates {numer += h[s]*p, denom += p} into g_acc[d].
__global__ void k_edge1(const void* __restrict__ ei, int E, int N) {
    int is64 = probe_is64((const int*)ei, E);
    int base = (blockIdx.x * blockDim.x + threadIdx.x) * 4;
    if (base >= E) return;
    if (base + 4 <= E) {
        int s[4], d[4];
        load_edges4(ei, E, N, base, is64, s, d);
        float2 sp[4];
        float  ad[4];
#pragma unroll
        for (int k = 0; k < 4; k++) { sp[k] = g_spack[s[k]]; ad[k] = g_ad[d[k]]; }
        float p[4];
#pragma unroll
        for (int k = 0; k < 4; k++) p[k] = expf(lrelu(sp[k].x + ad[k]));
        *reinterpret_cast<float4*>(g_p + base) = make_float4(p[0], p[1], p[2], p[3]);
#pragma unroll
        for (int k = 0; k < 4; k++)
            red_add_v2(&g_acc[d[k]], sp[k].y * p[k], p[k]);
    } else {
        for (int j = base; j < E; j++) {
            int s, d;
            load_edge1(ei, E, N, j, is64, s, d);
            float2 sp = g_spack[s];
            float p = expf(lrelu(sp.x + g_ad[d]));
            g_p[j] = p;
            red_add_v2(&g_acc[d], sp.y * p, p);
        }
    }
}

// KB (fused): blocks [0, nb2) finalize scores + self-loop slots; blocks
// [nb2, nb2+eblocks) produce per-edge alpha (gather denom directly).
__global__ void k_fuseB(float* __restrict__ out, const float* __restrict__ bias,
                        int E, int N, long long Ell, long long M, int full, int nb2) {
    int tid = threadIdx.x;
    if ((int)blockIdx.x < nb2) {
        int i = blockIdx.x * blockDim.x + tid;
        if (i >= N) return;
        float2 acc = g_acc[i];
        float inv = 1.0f / (acc.y + 1e-16f);
        out[i] = bias[0] + acc.x * inv;
        if (full) {
            size_t base = (size_t)N;
            float fi = (float)i;
            out[base + Ell + i]         = fi;               // src, self-loop slot
            out[base + M + Ell + i]     = fi;               // dst, self-loop slot
            out[base + 2 * M + Ell + i] = g_eself[i] * inv; // alpha, self-loop slot
        }
    } else {
        // edge-alpha role: read dst back from out's float-dst stream (exact < 2^24)
        int base = (((int)blockIdx.x - nb2) * blockDim.x + tid) * 4;
        if (base >= E) return;
        size_t b = (size_t)N + base;
        if (base + 4 <= E) {
            float4 fd = *reinterpret_cast<const float4*>(out + b + M);
            float4 pv = *reinterpret_cast<const float4*>(g_p + base);
            int d0 = __float2int_rz(fd.x), d1 = __float2int_rz(fd.y);
            int d2 = __float2int_rz(fd.z), d3 = __float2int_rz(fd.w);
            float4 fa = make_float4(pv.x / (g_acc[d0].y + 1e-16f),
                                    pv.y / (g_acc[d1].y + 1e-16f),
                                    pv.z / (g_acc[d2].y + 1e-16f),
                                    pv.w / (g_acc[d3].y + 1e-16f));
            __stcs(reinterpret_cast<float4*>(out + b + 2 * M), fa);
        } else {
            for (int j = base; j < E; j++) {
                int d = __float2int_rz(out[(size_t)N + M + j]);
                out[(size_t)N + 2 * M + j] = g_p[j] / (g_acc[d].y + 1e-16f);
            }
        }
    }
}

extern "C" void kernel_launch(void* const* d_in, const int* in_sizes, int n_in,
                              void* d_out, int out_size) {
    const float* x       = (const float*)d_in[0];
    const void*  ei      = d_in[1];
    const float* W       = (const float*)d_in[2];
    const float* att_src = (const float*)d_in[3];
    const float* att_dst = (const float*)d_in[4];
    const float* bias    = (const float*)d_in[5];

    int N = in_sizes[0] / 128;
    int E = in_sizes[1] / 2;
    long long M = (long long)E + N;
    int full = ((long long)out_size >= (long long)N + 3 * M) ? 1 : 0;
    float* out = (float*)d_out;

    int eth = (E + 3) / 4;
    int eblocks = (eth + 255) / 256;              // edge-role blocks (4 edges/thread)
    int nblocks1 = (N + 7) / 8;                   // node1: 8 warps/block, 1 node/warp
    int nblocks2 = (N + 255) / 256;               // node2: 1 node/thread

    int ebA = full ? eblocks : 0;
    k_fuseA<<<ebA + nblocks1, 256>>>(ei, x, W, att_src, att_dst, out, E, N, M, ebA);
    k_edge1<<<eblocks, 256>>>(ei, E, N);
    int ebB = full ? eblocks : 0;
    k_fuseB<<<nblocks2 + ebB, 256>>>(out, bias, E, N, (long long)E, M, full, nblocks2);
}